// round 5
// baseline (speedup 1.0000x reference)
#include <cuda_runtime.h>
#include <cuda_bf16.h>
#include <math.h>
#include <stdint.h>

#define NQ    20
#define DIM   (1u << NQ)
#define BATCH 4
#define LOWC  4

// ---------------- global scratch ----------------
static __device__ float2 g_psi[(size_t)BATCH * DIM];   // intermediate state
static __device__ uint2  g_pk [(size_t)BATCH * DIM];   // packed bf16 (reHi,reLo | imHi,imLo)
static __device__ float2 g_fused[NQ - 1][16];          // 19 fully-fused 4x4 gates

// ---------------- complex helpers ----------------
__device__ __forceinline__ float2 cmul(float2 a, float2 b) {
    return make_float2(a.x * b.x - a.y * b.y, a.x * b.y + a.y * b.x);
}
__device__ __forceinline__ float2 cadd(float2 a, float2 b) {
    return make_float2(a.x + b.x, a.y + b.y);
}
__device__ void mat2mul(const float2* A, const float2* B, float2* C) {
    for (int i = 0; i < 2; i++)
        for (int j = 0; j < 2; j++) {
            float2 s = make_float2(0.f, 0.f);
            for (int k = 0; k < 2; k++) s = cadd(s, cmul(A[i * 2 + k], B[k * 2 + j]));
            C[i * 2 + j] = s;
        }
}
__device__ void mat4mul(const float2* A, const float2* B, float2* C) {
    for (int i = 0; i < 4; i++)
        for (int j = 0; j < 4; j++) {
            float2 s = make_float2(0.f, 0.f);
            for (int k = 0; k < 4; k++) s = cadd(s, cmul(A[i * 4 + k], B[k * 4 + j]));
            C[i * 4 + j] = s;
        }
}
__device__ void kron22(const float2* A, const float2* B, float2* C) {
    for (int i2 = 0; i2 < 2; i2++)
        for (int i1 = 0; i1 < 2; i1++)
            for (int j2 = 0; j2 < 2; j2++)
                for (int j1 = 0; j1 < 2; j1++)
                    C[(i2 * 2 + i1) * 4 + (j2 * 2 + j1)] = cmul(A[i2 * 2 + j2], B[i1 * 2 + j1]);
}

// ---------------- gate precompute ----------------
__global__ void precompute_gates(const float* __restrict__ w) {
    const float WM = 0.6324555320336759f;  // sqrt(2/5)
    __shared__ float2 U1[NQ][4];
    __shared__ float2 U2[NQ][4];
    int t = threadIdx.x;
    if (t < NQ) {
        for (int layer = 0; layer < 2; layer++) {
            int base = (layer == 0) ? 0 : (6 * NQ - 3);
            float tx = w[base + 3 * t]     * WM;
            float ty = w[base + 3 * t + 1] * WM;
            float tz = w[base + 3 * t + 2] * WM;
            float cx = cosf(0.5f * tx), sx = sinf(0.5f * tx);
            float cy = cosf(0.5f * ty), sy = sinf(0.5f * ty);
            float cz = cosf(0.5f * tz), sz = sinf(0.5f * tz);
            float2 Rx[4] = { {cx,0.f}, {0.f,-sx}, {0.f,-sx}, {cx,0.f} };
            float2 Ry[4] = { {cy,0.f}, {-sy,0.f}, {sy,0.f},  {cy,0.f} };
            float2 Rz[4] = { {cz,-sz}, {0.f,0.f}, {0.f,0.f}, {cz,sz} };
            float2 T[4], U[4];
            mat2mul(Ry, Rx, T);
            mat2mul(Rz, T, U);
            float2* dst = (layer == 0) ? U1[t] : U2[t];
            for (int i = 0; i < 4; i++) dst[i] = U[i];
        }
    }
    __syncthreads();
    if (t < NQ - 1) {
        float a = w[3 * NQ + 3 * t]     * WM;
        float b = w[3 * NQ + 3 * t + 1] * WM;
        float c = w[3 * NQ + 3 * t + 2] * WM;
        float ca = cosf(0.5f * a), sa = sinf(0.5f * a);
        float cb = cosf(0.5f * b), sb = sinf(0.5f * b);
        float cc = cosf(0.5f * c), sc = sinf(0.5f * c);
        float2 Rxx[16], Ryy[16], Rzz[16];
        for (int i = 0; i < 16; i++) {
            Rxx[i] = make_float2(0.f, 0.f);
            Ryy[i] = make_float2(0.f, 0.f);
            Rzz[i] = make_float2(0.f, 0.f);
        }
        for (int i = 0; i < 4; i++) {
            Rxx[i * 4 + i] = make_float2(ca, 0.f);
            Ryy[i * 4 + i] = make_float2(cb, 0.f);
        }
        Rxx[3]  = make_float2(0.f, -sa);
        Rxx[6]  = make_float2(0.f, -sa);
        Rxx[9]  = make_float2(0.f, -sa);
        Rxx[12] = make_float2(0.f, -sa);
        Ryy[3]  = make_float2(0.f,  sb);
        Ryy[6]  = make_float2(0.f, -sb);
        Ryy[9]  = make_float2(0.f, -sb);
        Ryy[12] = make_float2(0.f,  sb);
        Rzz[0]  = make_float2(cc, -sc);
        Rzz[5]  = make_float2(cc,  sc);
        Rzz[10] = make_float2(cc,  sc);
        Rzz[15] = make_float2(cc, -sc);
        float2 T[16], Bq[16];
        mat4mul(Ryy, Rxx, T);
        mat4mul(Rzz, T, Bq);

        float2 I2m[4] = { {1.f,0.f},{0.f,0.f},{0.f,0.f},{1.f,0.f} };
        float2 R[16], G[16];
        if (t == 0) kron22(U1[0], U1[1], R);
        else        kron22(I2m, U1[t + 1], R);
        mat4mul(Bq, R, G);
        if (t >= 10) {
            float2 L[16], G2[16];
            if (t == 18) kron22(U2[18], U2[19], L);
            else         kron22(U2[t], I2m, L);
            mat4mul(L, G, G2);
            for (int i = 0; i < 16; i++) G[i] = G2[i];
        }
        for (int i = 0; i < 16; i++) g_fused[t][i] = G[i];
    }
}

// ---------------- 2q gate on shared tile ----------------
__device__ __forceinline__ void apply2q(float2* s, int nquads, int pl,
                                        const float2* __restrict__ Mg,
                                        int tid, int nth) {
    float2 m[16];
#pragma unroll
    for (int i = 0; i < 16; i++) m[i] = Mg[i];
    for (int p = tid; p < nquads; p += nth) {
        int lowm = p & ((1 << pl) - 1);
        int i0 = ((p >> pl) << (pl + 2)) | lowm;
        float2 v0 = s[i0];
        float2 v1 = s[i0 | (1 << pl)];
        float2 v2 = s[i0 | (2 << pl)];
        float2 v3 = s[i0 | (3 << pl)];
#pragma unroll
        for (int j = 0; j < 4; j++) {
            float2 m0 = m[j * 4], m1 = m[j * 4 + 1], m2 = m[j * 4 + 2], m3 = m[j * 4 + 3];
            float rr = m0.x * v0.x - m0.y * v0.y + m1.x * v1.x - m1.y * v1.y
                     + m2.x * v2.x - m2.y * v2.y + m3.x * v3.x - m3.y * v3.y;
            float ri = m0.x * v0.y + m0.y * v0.x + m1.x * v1.y + m1.y * v1.x
                     + m2.x * v2.y + m2.y * v2.x + m3.x * v3.y + m3.y * v3.x;
            s[i0 | (j << pl)] = make_float2(rr, ri);
        }
    }
}

// ---------------- Pass H ----------------
__global__ void pass_high(const float* __restrict__ x) {
    __shared__ float2 s[1024 * LOWC];
    const int b    = blockIdx.y;
    const int low0 = blockIdx.x * LOWC;
    const int tid  = threadIdx.x;
    const float* xb = x + (size_t)b * DIM;

    for (int e = tid; e < 1024 * LOWC; e += blockDim.x) {
        int l = e & (LOWC - 1), h = e >> 2;
        s[e] = make_float2(xb[h * 1024 + low0 + l], 0.f);
    }
    __syncthreads();
    for (int q = 0; q < 9; q++) {
        apply2q(s, 1024, (8 - q) + 2, g_fused[q], tid, blockDim.x);
        __syncthreads();
    }
    float2* pb = g_psi + (size_t)b * DIM;
    for (int e = tid; e < 1024 * LOWC; e += blockDim.x) {
        int l = e & (LOWC - 1), h = e >> 2;
        pb[h * 1024 + low0 + l] = s[e];
    }
}

// ---------------- bf16 split pack ----------------
__device__ __forceinline__ uint32_t pack_split(float v) {
    __nv_bfloat16 h = __float2bfloat16(v);
    float hf = __bfloat162float(h);
    __nv_bfloat16 l = __float2bfloat16(v - hf);
    unsigned short hs = *reinterpret_cast<unsigned short*>(&h);
    unsigned short ls = *reinterpret_cast<unsigned short*>(&l);
    return ((uint32_t)ls << 16) | (uint32_t)hs;
}

// ---------------- Pass L ----------------
__global__ void pass_low() {
    __shared__ float2 s[2048];
    const int b = blockIdx.y;
    const size_t base = (size_t)b * DIM + (size_t)blockIdx.x * 2048;
    const int tid = threadIdx.x;

    for (int e = tid; e < 2048; e += blockDim.x) s[e] = g_psi[base + e];
    __syncthreads();
    for (int q = 9; q < 19; q++) {
        apply2q(s, 512, 18 - q, g_fused[q], tid, blockDim.x);
        __syncthreads();
    }
    for (int e = tid; e < 2048; e += blockDim.x) {
        float2 v = s[e];
        g_pk[base + e] = make_uint2(pack_split(v.x), pack_split(v.y));
    }
}

// ---------------- rdm GEMM v4: cp.async 3-stage pipeline, 2 CTAs/SM ----------------
#define ASTR 66
#define BSTR 130
#define A_BUF (16 * ASTR)
#define B_BUF (16 * BSTR)
#define STAGE_BUF (A_BUF + B_BUF)
#define STAGES 3
#define GEMM_SMEM (STAGES * STAGE_BUF * 8)

__device__ __forceinline__ void mma_bf16(float* d, uint32_t a0, uint32_t a1,
                                         uint32_t a2, uint32_t a3,
                                         uint32_t b0, uint32_t b1) {
    asm volatile(
        "mma.sync.aligned.m16n8k16.row.col.f32.bf16.bf16.f32 "
        "{%0,%1,%2,%3},{%4,%5,%6,%7},{%8,%9},{%0,%1,%2,%3};"
        : "+f"(d[0]), "+f"(d[1]), "+f"(d[2]), "+f"(d[3])
        : "r"(a0), "r"(a1), "r"(a2), "r"(a3), "r"(b0), "r"(b1));
}

__device__ __forceinline__ void cp_async16(void* smem_ptr, const void* gptr) {
    uint32_t sa = (uint32_t)__cvta_generic_to_shared(smem_ptr);
    asm volatile("cp.async.cg.shared.global [%0], [%1], 16;" :: "r"(sa), "l"(gptr));
}
__device__ __forceinline__ void cp_commit() {
    asm volatile("cp.async.commit_group;");
}
__device__ __forceinline__ void cp_wait1() {
    asm volatile("cp.async.wait_group 1;");
}

__global__ void __launch_bounds__(256, 2) rdm_gemm(float* __restrict__ out) {
    extern __shared__ uint2 sm[];

    // decode linear block -> (col tile tcc of 128, row tile ta of 64), ta <= 2*tcc+1
    int tcc = 0, rem = blockIdx.x;
    while (rem >= 2 * tcc + 2) { rem -= 2 * tcc + 2; tcc++; }
    int ta = rem;

    const int b = blockIdx.y;
    const uint2* P = g_pk + (size_t)b * DIM;
    const int a0b = ta * 64, c0b = tcc * 128;
    const int tid  = threadIdx.x;
    const int wid  = tid >> 5;
    const int lane = tid & 31;
    const int g    = lane >> 2;
    const int t4   = lane & 3;
    const int warpM = wid & 1;     // a offset 0/32
    const int warpN = wid >> 1;    // c offset 0/32/64/96

    float accR[2][4][4] = {};
    float accI[2][4][4] = {};

    // issue one k-tile stage of async copies (A: 2x16B, B: 4x16B per thread)
    auto issue_stage = [&](int kt, int s) {
        uint2* bA = sm + s * STAGE_BUF;
        uint2* bB = bA + A_BUF;
        const uint2* Pk = P + (size_t)kt * 16 * 1024;
#pragma unroll
        for (int j = 0; j < 2; j++) {
            int p = tid + j * 256;            // pair index 0..511
            int i = (2 * p) & 63, kk = (2 * p) >> 6;
            cp_async16(&bA[kk * ASTR + i], &Pk[(size_t)kk * 1024 + a0b + i]);
        }
#pragma unroll
        for (int j = 0; j < 4; j++) {
            int p = tid + j * 256;            // pair index 0..1023
            int i = (2 * p) & 127, kk = (2 * p) >> 7;
            cp_async16(&bB[kk * BSTR + i], &Pk[(size_t)kk * 1024 + c0b + i]);
        }
        cp_commit();
    };

    issue_stage(0, 0);
    issue_stage(1, 1);

    for (int kt = 0; kt < 64; kt++) {
        cp_wait1();                 // stage kt is resident
        __syncthreads();            // everyone sees it; prior compute done (buffer reuse safe)

        uint2* bufA = sm + (kt % STAGES) * STAGE_BUF;
        uint2* bufB = bufA + A_BUF;

        // ---- build A fragments: [mi][0=rHi 1=rLo 2=iHi 3=iLo][reg] ----
        uint32_t Af[2][4][4];
#pragma unroll
        for (int mi = 0; mi < 2; mi++) {
            int row0 = warpM * 32 + mi * 16 + g;
#pragma unroll
            for (int pos = 0; pos < 4; pos++) {
                int row = row0 + ((pos & 1) ? 8 : 0);
                int kk  = 2 * t4 + ((pos & 2) ? 8 : 0);
                uint2 e0 = bufA[kk * ASTR + row];
                uint2 e1 = bufA[(kk + 1) * ASTR + row];
                Af[mi][0][pos] = __byte_perm(e0.x, e1.x, 0x5410);
                Af[mi][1][pos] = __byte_perm(e0.x, e1.x, 0x7632);
                Af[mi][2][pos] = __byte_perm(e0.y, e1.y, 0x5410);
                Af[mi][3][pos] = __byte_perm(e0.y, e1.y, 0x7632);
            }
        }

#pragma unroll
        for (int ni = 0; ni < 4; ni++) {
            int col = warpN * 32 + ni * 8 + g;
            int kk = 2 * t4;
            uint2 e0 = bufB[kk * BSTR + col];
            uint2 e1 = bufB[(kk + 1) * BSTR + col];
            uint2 e2 = bufB[(kk + 8) * BSTR + col];
            uint2 e3 = bufB[(kk + 9) * BSTR + col];
            uint32_t BrH[2], BrL[2], BiH[2], BiL[2], BnH[2], BnL[2];
            BrH[0] = __byte_perm(e0.x, e1.x, 0x5410);
            BrL[0] = __byte_perm(e0.x, e1.x, 0x7632);
            BiH[0] = __byte_perm(e0.y, e1.y, 0x5410);
            BiL[0] = __byte_perm(e0.y, e1.y, 0x7632);
            BrH[1] = __byte_perm(e2.x, e3.x, 0x5410);
            BrL[1] = __byte_perm(e2.x, e3.x, 0x7632);
            BiH[1] = __byte_perm(e2.y, e3.y, 0x5410);
            BiL[1] = __byte_perm(e2.y, e3.y, 0x7632);
            BnH[0] = BiH[0] ^ 0x80008000u;
            BnL[0] = BiL[0] ^ 0x80008000u;
            BnH[1] = BiH[1] ^ 0x80008000u;
            BnL[1] = BiL[1] ^ 0x80008000u;
#pragma unroll
            for (int mi = 0; mi < 2; mi++) {
                float* dR = accR[mi][ni];
                float* dI = accI[mi][ni];
                mma_bf16(dR, Af[mi][0][0], Af[mi][0][1], Af[mi][0][2], Af[mi][0][3], BrH[0], BrH[1]);
                mma_bf16(dR, Af[mi][0][0], Af[mi][0][1], Af[mi][0][2], Af[mi][0][3], BrL[0], BrL[1]);
                mma_bf16(dR, Af[mi][1][0], Af[mi][1][1], Af[mi][1][2], Af[mi][1][3], BrH[0], BrH[1]);
                mma_bf16(dR, Af[mi][2][0], Af[mi][2][1], Af[mi][2][2], Af[mi][2][3], BiH[0], BiH[1]);
                mma_bf16(dR, Af[mi][2][0], Af[mi][2][1], Af[mi][2][2], Af[mi][2][3], BiL[0], BiL[1]);
                mma_bf16(dR, Af[mi][3][0], Af[mi][3][1], Af[mi][3][2], Af[mi][3][3], BiH[0], BiH[1]);
                mma_bf16(dI, Af[mi][2][0], Af[mi][2][1], Af[mi][2][2], Af[mi][2][3], BrH[0], BrH[1]);
                mma_bf16(dI, Af[mi][2][0], Af[mi][2][1], Af[mi][2][2], Af[mi][2][3], BrL[0], BrL[1]);
                mma_bf16(dI, Af[mi][3][0], Af[mi][3][1], Af[mi][3][2], Af[mi][3][3], BrH[0], BrH[1]);
                mma_bf16(dI, Af[mi][0][0], Af[mi][0][1], Af[mi][0][2], Af[mi][0][3], BnH[0], BnH[1]);
                mma_bf16(dI, Af[mi][0][0], Af[mi][0][1], Af[mi][0][2], Af[mi][0][3], BnL[0], BnL[1]);
                mma_bf16(dI, Af[mi][1][0], Af[mi][1][1], Af[mi][1][2], Af[mi][1][3], BnH[0], BnH[1]);
            }
        }
        __syncthreads();            // done reading stage kt's buffer

        if (kt + 2 < 64) issue_stage(kt + 2, (kt + 2) % STAGES);
        else             cp_commit();   // empty group keeps wait_group arithmetic valid
    }

    // ---- epilogue: exactly-once writes via per-element guards ----
    float2* out2 = (float2*)out;
#pragma unroll
    for (int mi = 0; mi < 2; mi++)
#pragma unroll
        for (int ni = 0; ni < 4; ni++)
#pragma unroll
            for (int r = 0; r < 4; r++) {
                int a = a0b + warpM * 32 + mi * 16 + g + ((r & 2) ? 8 : 0);
                int c = c0b + warpN * 32 + ni * 8 + 2 * t4 + (r & 1);
                float vr = accR[mi][ni][r];
                float vi = accI[mi][ni][r];
                if (a <= c)
                    out2[(size_t)(b * 1024 + a) * 1024 + c] = make_float2(vr, vi);
                if (a < c)
                    out2[(size_t)(b * 1024 + c) * 1024 + a] = make_float2(vr, -vi);
            }
}

// ---------------- launch ----------------
extern "C" void kernel_launch(void* const* d_in, const int* in_sizes, int n_in,
                              void* d_out, int out_size) {
    const float* x = (const float*)d_in[0];
    const float* w = (const float*)d_in[1];
    float* out = (float*)d_out;

    cudaFuncSetAttribute(rdm_gemm, cudaFuncAttributeMaxDynamicSharedMemorySize, GEMM_SMEM);

    precompute_gates<<<1, 32>>>(w);
    pass_high<<<dim3(1024 / LOWC, BATCH), 256>>>(x);
    pass_low<<<dim3(512, BATCH), 256>>>();
    rdm_gemm<<<dim3(72, BATCH), 256, GEMM_SMEM>>>(out);
}

// round 7
// speedup vs baseline: 1.0284x; 1.0284x over previous
#include <cuda_runtime.h>
#include <cuda_fp16.h>
#include <math.h>
#include <stdint.h>

#define NQ    20
#define DIM   (1u << NQ)
#define BATCH 4
#define LOWC  4

// ---------------- global scratch ----------------
static __device__ float2 g_psi[(size_t)BATCH * DIM];          // state vector
// 7 fp16 planes [plane][b][col][k], k contiguous:
// 0=rH 1=rL 2=iH 3=iL 4=dH 5=dL 6=sH   (d = i - r, s = r + i)
static __device__ __half g_tp[(size_t)7 * BATCH * DIM];
static __device__ float2 g_fused[NQ - 1][16];                 // fused 4x4 gates

// ---------------- complex helpers ----------------
__device__ __forceinline__ float2 cmul(float2 a, float2 b) {
    return make_float2(a.x * b.x - a.y * b.y, a.x * b.y + a.y * b.x);
}
__device__ __forceinline__ float2 cadd(float2 a, float2 b) {
    return make_float2(a.x + b.x, a.y + b.y);
}
__device__ void mat2mul(const float2* A, const float2* B, float2* C) {
    for (int i = 0; i < 2; i++)
        for (int j = 0; j < 2; j++) {
            float2 s = make_float2(0.f, 0.f);
            for (int k = 0; k < 2; k++) s = cadd(s, cmul(A[i * 2 + k], B[k * 2 + j]));
            C[i * 2 + j] = s;
        }
}
__device__ void mat4mul(const float2* A, const float2* B, float2* C) {
    for (int i = 0; i < 4; i++)
        for (int j = 0; j < 4; j++) {
            float2 s = make_float2(0.f, 0.f);
            for (int k = 0; k < 4; k++) s = cadd(s, cmul(A[i * 4 + k], B[k * 4 + j]));
            C[i * 4 + j] = s;
        }
}
__device__ void kron22(const float2* A, const float2* B, float2* C) {
    for (int i2 = 0; i2 < 2; i2++)
        for (int i1 = 0; i1 < 2; i1++)
            for (int j2 = 0; j2 < 2; j2++)
                for (int j1 = 0; j1 < 2; j1++)
                    C[(i2 * 2 + i1) * 4 + (j2 * 2 + j1)] = cmul(A[i2 * 2 + j2], B[i1 * 2 + j1]);
}

// ---------------- gate precompute ----------------
__global__ void precompute_gates(const float* __restrict__ w) {
    const float WM = 0.6324555320336759f;  // sqrt(2/5)
    __shared__ float2 U1[NQ][4];
    __shared__ float2 U2[NQ][4];
    int t = threadIdx.x;
    if (t < NQ) {
        for (int layer = 0; layer < 2; layer++) {
            int base = (layer == 0) ? 0 : (6 * NQ - 3);
            float tx = w[base + 3 * t]     * WM;
            float ty = w[base + 3 * t + 1] * WM;
            float tz = w[base + 3 * t + 2] * WM;
            float cx = cosf(0.5f * tx), sx = sinf(0.5f * tx);
            float cy = cosf(0.5f * ty), sy = sinf(0.5f * ty);
            float cz = cosf(0.5f * tz), sz = sinf(0.5f * tz);
            float2 Rx[4] = { {cx,0.f}, {0.f,-sx}, {0.f,-sx}, {cx,0.f} };
            float2 Ry[4] = { {cy,0.f}, {-sy,0.f}, {sy,0.f},  {cy,0.f} };
            float2 Rz[4] = { {cz,-sz}, {0.f,0.f}, {0.f,0.f}, {cz,sz} };
            float2 T[4], U[4];
            mat2mul(Ry, Rx, T);
            mat2mul(Rz, T, U);
            float2* dst = (layer == 0) ? U1[t] : U2[t];
            for (int i = 0; i < 4; i++) dst[i] = U[i];
        }
    }
    __syncthreads();
    if (t < NQ - 1) {
        float a = w[3 * NQ + 3 * t]     * WM;
        float b = w[3 * NQ + 3 * t + 1] * WM;
        float c = w[3 * NQ + 3 * t + 2] * WM;
        float ca = cosf(0.5f * a), sa = sinf(0.5f * a);
        float cb = cosf(0.5f * b), sb = sinf(0.5f * b);
        float cc = cosf(0.5f * c), sc = sinf(0.5f * c);
        float2 Rxx[16], Ryy[16], Rzz[16];
        for (int i = 0; i < 16; i++) {
            Rxx[i] = make_float2(0.f, 0.f);
            Ryy[i] = make_float2(0.f, 0.f);
            Rzz[i] = make_float2(0.f, 0.f);
        }
        for (int i = 0; i < 4; i++) {
            Rxx[i * 4 + i] = make_float2(ca, 0.f);
            Ryy[i * 4 + i] = make_float2(cb, 0.f);
        }
        Rxx[3]  = make_float2(0.f, -sa);
        Rxx[6]  = make_float2(0.f, -sa);
        Rxx[9]  = make_float2(0.f, -sa);
        Rxx[12] = make_float2(0.f, -sa);
        Ryy[3]  = make_float2(0.f,  sb);
        Ryy[6]  = make_float2(0.f, -sb);
        Ryy[9]  = make_float2(0.f, -sb);
        Ryy[12] = make_float2(0.f,  sb);
        Rzz[0]  = make_float2(cc, -sc);
        Rzz[5]  = make_float2(cc,  sc);
        Rzz[10] = make_float2(cc,  sc);
        Rzz[15] = make_float2(cc, -sc);
        float2 T[16], Bq[16];
        mat4mul(Ryy, Rxx, T);
        mat4mul(Rzz, T, Bq);

        float2 I2m[4] = { {1.f,0.f},{0.f,0.f},{0.f,0.f},{1.f,0.f} };
        float2 R[16], G[16];
        if (t == 0) kron22(U1[0], U1[1], R);
        else        kron22(I2m, U1[t + 1], R);
        mat4mul(Bq, R, G);
        if (t >= 10) {
            float2 L[16], G2[16];
            if (t == 18) kron22(U2[18], U2[19], L);
            else         kron22(U2[t], I2m, L);
            mat4mul(L, G, G2);
            for (int i = 0; i < 16; i++) G[i] = G2[i];
        }
        for (int i = 0; i < 16; i++) g_fused[t][i] = G[i];
    }
}

// ---------------- 2q gate on shared tile ----------------
__device__ __forceinline__ void apply2q(float2* s, int nquads, int pl,
                                        const float2* __restrict__ Mg,
                                        int tid, int nth) {
    float2 m[16];
#pragma unroll
    for (int i = 0; i < 16; i++) m[i] = Mg[i];
    for (int p = tid; p < nquads; p += nth) {
        int lowm = p & ((1 << pl) - 1);
        int i0 = ((p >> pl) << (pl + 2)) | lowm;
        float2 v0 = s[i0];
        float2 v1 = s[i0 | (1 << pl)];
        float2 v2 = s[i0 | (2 << pl)];
        float2 v3 = s[i0 | (3 << pl)];
#pragma unroll
        for (int j = 0; j < 4; j++) {
            float2 m0 = m[j * 4], m1 = m[j * 4 + 1], m2 = m[j * 4 + 2], m3 = m[j * 4 + 3];
            float rr = m0.x * v0.x - m0.y * v0.y + m1.x * v1.x - m1.y * v1.y
                     + m2.x * v2.x - m2.y * v2.y + m3.x * v3.x - m3.y * v3.y;
            float ri = m0.x * v0.y + m0.y * v0.x + m1.x * v1.y + m1.y * v1.x
                     + m2.x * v2.y + m2.y * v2.x + m3.x * v3.y + m3.y * v3.x;
            s[i0 | (j << pl)] = make_float2(rr, ri);
        }
    }
}

// ---------------- Pass H ----------------
__global__ void pass_high(const float* __restrict__ x) {
    __shared__ float2 s[1024 * LOWC];
    const int b    = blockIdx.y;
    const int low0 = blockIdx.x * LOWC;
    const int tid  = threadIdx.x;
    const float* xb = x + (size_t)b * DIM;

    for (int e = tid; e < 1024 * LOWC; e += blockDim.x) {
        int l = e & (LOWC - 1), h = e >> 2;
        s[e] = make_float2(xb[h * 1024 + low0 + l], 0.f);
    }
    __syncthreads();
    for (int q = 0; q < 9; q++) {
        apply2q(s, 1024, (8 - q) + 2, g_fused[q], tid, blockDim.x);
        __syncthreads();
    }
    float2* pb = g_psi + (size_t)b * DIM;
    for (int e = tid; e < 1024 * LOWC; e += blockDim.x) {
        int l = e & (LOWC - 1), h = e >> 2;
        pb[h * 1024 + low0 + l] = s[e];
    }
}

// ---------------- Pass L ----------------
__global__ void pass_low() {
    __shared__ float2 s[2048];
    const int b = blockIdx.y;
    const size_t base = (size_t)b * DIM + (size_t)blockIdx.x * 2048;
    const int tid = threadIdx.x;

    for (int e = tid; e < 2048; e += blockDim.x) s[e] = g_psi[base + e];
    __syncthreads();
    for (int q = 9; q < 19; q++) {
        apply2q(s, 512, 18 - q, g_fused[q], tid, blockDim.x);
        __syncthreads();
    }
    for (int e = tid; e < 2048; e += blockDim.x) g_psi[base + e] = s[e];
}

// ---------------- transpose + fp16 split into 7 planes ----------------
__device__ __forceinline__ uint32_t pk2(float a, float b) {
    __half ha = __float2half_rn(a), hb = __float2half_rn(b);
    return (uint32_t)__half_as_ushort(ha) | ((uint32_t)__half_as_ushort(hb) << 16);
}

__global__ void transpose_split() {
    __shared__ float2 s[64][65];
    const int b  = blockIdx.y;
    const int k0 = (blockIdx.x >> 4) * 64;   // t-tile
    const int c0 = (blockIdx.x & 15) * 64;   // a-tile
    const int tid = threadIdx.x;
    const float2* pb = g_psi + ((size_t)b << 20);

    for (int e = tid; e < 4096; e += 256) {
        int r = e >> 6, j = e & 63;
        s[r][j] = pb[(size_t)(k0 + r) * 1024 + c0 + j];
    }
    __syncthreads();

    uint32_t* tp32 = (uint32_t*)g_tp;
    const size_t pstride = (size_t)BATCH << 19;  // uint32s per plane
    for (int e = tid; e < 2048; e += 256) {
        int cc = e >> 5, kp = e & 31;
        float2 v0 = s[2 * kp][cc];
        float2 v1 = s[2 * kp + 1][cc];
        float r0 = v0.x, i0 = v0.y, r1 = v1.x, i1 = v1.y;
        float d0 = i0 - r0, d1 = i1 - r1;
        float s0 = r0 + i0, s1 = r1 + i1;
        __half rh0 = __float2half_rn(r0), rh1 = __float2half_rn(r1);
        __half ih0 = __float2half_rn(i0), ih1 = __float2half_rn(i1);
        __half dh0 = __float2half_rn(d0), dh1 = __float2half_rn(d1);
        float rl0 = r0 - __half2float(rh0), rl1 = r1 - __half2float(rh1);
        float il0 = i0 - __half2float(ih0), il1 = i1 - __half2float(ih1);
        float dl0 = d0 - __half2float(dh0), dl1 = d1 - __half2float(dh1);
        size_t ci = ((size_t)b << 19) + ((size_t)(c0 + cc) << 9) + (k0 >> 1) + kp;
        tp32[0 * pstride + ci] = (uint32_t)__half_as_ushort(rh0) | ((uint32_t)__half_as_ushort(rh1) << 16);
        tp32[1 * pstride + ci] = pk2(rl0, rl1);
        tp32[2 * pstride + ci] = (uint32_t)__half_as_ushort(ih0) | ((uint32_t)__half_as_ushort(ih1) << 16);
        tp32[3 * pstride + ci] = pk2(il0, il1);
        tp32[4 * pstride + ci] = (uint32_t)__half_as_ushort(dh0) | ((uint32_t)__half_as_ushort(dh1) << 16);
        tp32[5 * pstride + ci] = pk2(dl0, dl1);
        tp32[6 * pstride + ci] = pk2(s0, s1);
    }
}

// ---------------- rdm GEMM v5: fp16 Gauss, 6 MMAs/output, cp.async 3-stage ----------------
// Block tile 64(a) x 128(c); warp tile 32x32; products t1=Ar*Br, t2=Ai*Bi,
// t3=(Ai-Ar)*(Br+Bi);  R=t1+t2, I=t3+t1-t2.
// A-side planes (2-term split): {rH,rL},{iH,iL},{dH,dL}; B-side hi only: {rH,iH,sH}.
#define COLB   48                       // smem col stride (bytes): conflict-free + 16B aligned
#define A_PL_B (64 * COLB)              // 3072
#define B_PL_B (128 * COLB)             // 6144
#define STG_B  (6 * A_PL_B + 3 * B_PL_B)  // 36864
#define NSTG   3
#define GEMM_SMEM (NSTG * STG_B)        // 110592

__device__ __forceinline__ void mma_f16(float* d, uint32_t a0, uint32_t a1,
                                        uint32_t a2, uint32_t a3,
                                        uint32_t b0, uint32_t b1) {
    asm volatile(
        "mma.sync.aligned.m16n8k16.row.col.f32.f16.f16.f32 "
        "{%0,%1,%2,%3},{%4,%5,%6,%7},{%8,%9},{%0,%1,%2,%3};"
        : "+f"(d[0]), "+f"(d[1]), "+f"(d[2]), "+f"(d[3])
        : "r"(a0), "r"(a1), "r"(a2), "r"(a3), "r"(b0), "r"(b1));
}
__device__ __forceinline__ void cp_async16(void* smem_ptr, const void* gptr) {
    uint32_t sa = (uint32_t)__cvta_generic_to_shared(smem_ptr);
    asm volatile("cp.async.cg.shared.global [%0], [%1], 16;" :: "r"(sa), "l"(gptr));
}
__device__ __forceinline__ void cp_commit() { asm volatile("cp.async.commit_group;"); }
__device__ __forceinline__ void cp_wait2()  { asm volatile("cp.async.wait_group 2;"); }

__global__ void __launch_bounds__(256) rdm_gemm(float* __restrict__ out) {
    extern __shared__ char smem[];

    // decode linear block -> (col tile tcc of 128, row tile ta of 64), ta <= 2*tcc+1
    int tcc = 0, rem = blockIdx.x;
    while (rem >= 2 * tcc + 2) { rem -= 2 * tcc + 2; tcc++; }
    int ta = rem;

    const int b = blockIdx.y;
    const int a0b = ta * 64, c0b = tcc * 128;
    const int tid  = threadIdx.x;
    const int wid  = tid >> 5;
    const int lane = tid & 31;
    const int g    = lane >> 2;
    const int t4   = lane & 3;
    const int warpM = wid & 1;     // a offset 0/32
    const int warpN = wid >> 1;    // c offset 0/32/64/96

    float acc[3][2][4][4] = {};    // [product][mi][ni][reg]

    // one stage = 6 A-planes (64 cols x 16k) + 3 B-planes (128 cols x 16k)
    auto stage = [&](int kt) {
        char* sb = smem + (kt % NSTG) * STG_B;
        const int khalf = kt * 16;
#pragma unroll
        for (int j = 0; j < 6; j++) {
            int cid = tid + j * 256;
            if (cid < 768) {                       // A: plane = cid/128
                int pl = cid >> 7;
                int rm = cid & 127;
                int col = rm >> 1, h = rm & 1;
                const __half* src = g_tp + (((size_t)pl * BATCH + b) << 20)
                                  + ((size_t)(a0b + col) << 10) + khalf + h * 8;
                cp_async16(sb + pl * A_PL_B + col * COLB + h * 16, src);
            } else {                               // B: planes {rH=0, iH=2, sH=6}
                int d2 = cid - 768;
                int pl = d2 >> 8;
                int rm = d2 & 255;
                int col = rm >> 1, h = rm & 1;
                int gp = (pl == 0) ? 0 : ((pl == 1) ? 2 : 6);
                const __half* src = g_tp + (((size_t)gp * BATCH + b) << 20)
                                  + ((size_t)(c0b + col) << 10) + khalf + h * 8;
                cp_async16(sb + 6 * A_PL_B + pl * B_PL_B + col * COLB + h * 16, src);
            }
        }
        cp_commit();
    };

    stage(0);
    stage(1);
    stage(2);

    for (int kt = 0; kt < 64; kt++) {
        cp_wait2();
        __syncthreads();
        const char* sb = smem + (kt % NSTG) * STG_B;

#pragma unroll
        for (int p = 0; p < 3; p++) {
            const char* paH = sb + (2 * p)     * A_PL_B;
            const char* paL = sb + (2 * p + 1) * A_PL_B;
            const char* pbH = sb + 6 * A_PL_B + p * B_PL_B;

            uint32_t Ah[2][4], Al[2][4];
#pragma unroll
            for (int mi = 0; mi < 2; mi++) {
                int off = (warpM * 32 + mi * 16 + g) * COLB + t4 * 4;
                Ah[mi][0] = *(const uint32_t*)(paH + off);
                Ah[mi][1] = *(const uint32_t*)(paH + off + 8 * COLB);
                Ah[mi][2] = *(const uint32_t*)(paH + off + 16);
                Ah[mi][3] = *(const uint32_t*)(paH + off + 8 * COLB + 16);
                Al[mi][0] = *(const uint32_t*)(paL + off);
                Al[mi][1] = *(const uint32_t*)(paL + off + 8 * COLB);
                Al[mi][2] = *(const uint32_t*)(paL + off + 16);
                Al[mi][3] = *(const uint32_t*)(paL + off + 8 * COLB + 16);
            }
            uint32_t Bf[4][2];
#pragma unroll
            for (int ni = 0; ni < 4; ni++) {
                int off = (warpN * 32 + ni * 8 + g) * COLB + t4 * 4;
                Bf[ni][0] = *(const uint32_t*)(pbH + off);
                Bf[ni][1] = *(const uint32_t*)(pbH + off + 16);
            }
            // hi sweep then lo sweep: same-acc reuse spaced 8 MMAs apart
#pragma unroll
            for (int ni = 0; ni < 4; ni++)
#pragma unroll
                for (int mi = 0; mi < 2; mi++)
                    mma_f16(acc[p][mi][ni], Ah[mi][0], Ah[mi][1], Ah[mi][2], Ah[mi][3],
                            Bf[ni][0], Bf[ni][1]);
#pragma unroll
            for (int ni = 0; ni < 4; ni++)
#pragma unroll
                for (int mi = 0; mi < 2; mi++)
                    mma_f16(acc[p][mi][ni], Al[mi][0], Al[mi][1], Al[mi][2], Al[mi][3],
                            Bf[ni][0], Bf[ni][1]);
        }
        __syncthreads();

        if (kt + 3 < 64) stage(kt + 3);
        else             cp_commit();     // keep wait_group arithmetic valid
    }

    // ---- epilogue: R = t1+t2, I = t3+t1-t2; exactly-once Hermitian writes ----
    float2* out2 = (float2*)out;
#pragma unroll
    for (int mi = 0; mi < 2; mi++)
#pragma unroll
        for (int ni = 0; ni < 4; ni++)
#pragma unroll
            for (int r = 0; r < 4; r++) {
                int a = a0b + warpM * 32 + mi * 16 + g + ((r & 2) ? 8 : 0);
                int c = c0b + warpN * 32 + ni * 8 + 2 * t4 + (r & 1);
                float t1 = acc[0][mi][ni][r];
                float t2 = acc[1][mi][ni][r];
                float t3 = acc[2][mi][ni][r];
                float vr = t1 + t2;
                float vi = t3 + t1 - t2;
                if (a <= c)
                    out2[(size_t)(b * 1024 + a) * 1024 + c] = make_float2(vr, vi);
                if (a < c)
                    out2[(size_t)(b * 1024 + c) * 1024 + a] = make_float2(vr, -vi);
            }
}

// ---------------- launch ----------------
extern "C" void kernel_launch(void* const* d_in, const int* in_sizes, int n_in,
                              void* d_out, int out_size) {
    const float* x = (const float*)d_in[0];
    const float* w = (const float*)d_in[1];
    float* out = (float*)d_out;

    cudaFuncSetAttribute(rdm_gemm, cudaFuncAttributeMaxDynamicSharedMemorySize, GEMM_SMEM);

    precompute_gates<<<1, 32>>>(w);
    pass_high<<<dim3(1024 / LOWC, BATCH), 256>>>(x);
    pass_low<<<dim3(512, BATCH), 256>>>();
    transpose_split<<<dim3(256, BATCH), 256>>>();
    rdm_gemm<<<dim3(72, BATCH), 256, GEMM_SMEM>>>(out);
}

// round 8
// speedup vs baseline: 1.1385x; 1.1070x over previous
#include <cuda_runtime.h>
#include <cuda_fp16.h>
#include <math.h>
#include <stdint.h>

#define NQ    20
#define DIM   (1u << NQ)
#define BATCH 4
#define LOWC  4
#define SMAP(i) ((i) + ((i) >> 3))   // padded smem index map (conflict-avoidance)

// ---------------- global scratch ----------------
static __device__ float2 g_psi[(size_t)BATCH * DIM];   // state after pass_high
// 7 packed-fp16 planes [plane][b][kpair][col], uint32 = {k even (lo), k odd (hi)}
// planes: 0=rH 1=rL 2=iH 3=iL 4=dH 5=dL 6=sH   (d = i - r, s = r + i)
static __device__ uint32_t g_tp32[(size_t)7 * BATCH * (DIM / 2)];
static __device__ float2 g_fused[NQ - 1][16];          // fused 4x4 gates
#define PSTR ((size_t)BATCH << 19)                     // uint32s per plane

// ---------------- complex helpers ----------------
__device__ __forceinline__ float2 cmul(float2 a, float2 b) {
    return make_float2(a.x * b.x - a.y * b.y, a.x * b.y + a.y * b.x);
}
__device__ __forceinline__ float2 cadd(float2 a, float2 b) {
    return make_float2(a.x + b.x, a.y + b.y);
}
__device__ void mat2mul(const float2* A, const float2* B, float2* C) {
    for (int i = 0; i < 2; i++)
        for (int j = 0; j < 2; j++) {
            float2 s = make_float2(0.f, 0.f);
            for (int k = 0; k < 2; k++) s = cadd(s, cmul(A[i * 2 + k], B[k * 2 + j]));
            C[i * 2 + j] = s;
        }
}
__device__ void mat4mul(const float2* A, const float2* B, float2* C) {
    for (int i = 0; i < 4; i++)
        for (int j = 0; j < 4; j++) {
            float2 s = make_float2(0.f, 0.f);
            for (int k = 0; k < 4; k++) s = cadd(s, cmul(A[i * 4 + k], B[k * 4 + j]));
            C[i * 4 + j] = s;
        }
}
__device__ void kron22(const float2* A, const float2* B, float2* C) {
    for (int i2 = 0; i2 < 2; i2++)
        for (int i1 = 0; i1 < 2; i1++)
            for (int j2 = 0; j2 < 2; j2++)
                for (int j1 = 0; j1 < 2; j1++)
                    C[(i2 * 2 + i1) * 4 + (j2 * 2 + j1)] = cmul(A[i2 * 2 + j2], B[i1 * 2 + j1]);
}

// ---------------- gate precompute ----------------
__global__ void precompute_gates(const float* __restrict__ w) {
    const float WM = 0.6324555320336759f;  // sqrt(2/5)
    __shared__ float2 U1[NQ][4];
    __shared__ float2 U2[NQ][4];
    int t = threadIdx.x;
    if (t < NQ) {
        for (int layer = 0; layer < 2; layer++) {
            int base = (layer == 0) ? 0 : (6 * NQ - 3);
            float tx = w[base + 3 * t]     * WM;
            float ty = w[base + 3 * t + 1] * WM;
            float tz = w[base + 3 * t + 2] * WM;
            float cx = cosf(0.5f * tx), sx = sinf(0.5f * tx);
            float cy = cosf(0.5f * ty), sy = sinf(0.5f * ty);
            float cz = cosf(0.5f * tz), sz = sinf(0.5f * tz);
            float2 Rx[4] = { {cx,0.f}, {0.f,-sx}, {0.f,-sx}, {cx,0.f} };
            float2 Ry[4] = { {cy,0.f}, {-sy,0.f}, {sy,0.f},  {cy,0.f} };
            float2 Rz[4] = { {cz,-sz}, {0.f,0.f}, {0.f,0.f}, {cz,sz} };
            float2 T[4], U[4];
            mat2mul(Ry, Rx, T);
            mat2mul(Rz, T, U);
            float2* dst = (layer == 0) ? U1[t] : U2[t];
            for (int i = 0; i < 4; i++) dst[i] = U[i];
        }
    }
    __syncthreads();
    if (t < NQ - 1) {
        float a = w[3 * NQ + 3 * t]     * WM;
        float b = w[3 * NQ + 3 * t + 1] * WM;
        float c = w[3 * NQ + 3 * t + 2] * WM;
        float ca = cosf(0.5f * a), sa = sinf(0.5f * a);
        float cb = cosf(0.5f * b), sb = sinf(0.5f * b);
        float cc = cosf(0.5f * c), sc = sinf(0.5f * c);
        float2 Rxx[16], Ryy[16], Rzz[16];
        for (int i = 0; i < 16; i++) {
            Rxx[i] = make_float2(0.f, 0.f);
            Ryy[i] = make_float2(0.f, 0.f);
            Rzz[i] = make_float2(0.f, 0.f);
        }
        for (int i = 0; i < 4; i++) {
            Rxx[i * 4 + i] = make_float2(ca, 0.f);
            Ryy[i * 4 + i] = make_float2(cb, 0.f);
        }
        Rxx[3]  = make_float2(0.f, -sa);
        Rxx[6]  = make_float2(0.f, -sa);
        Rxx[9]  = make_float2(0.f, -sa);
        Rxx[12] = make_float2(0.f, -sa);
        Ryy[3]  = make_float2(0.f,  sb);
        Ryy[6]  = make_float2(0.f, -sb);
        Ryy[9]  = make_float2(0.f, -sb);
        Ryy[12] = make_float2(0.f,  sb);
        Rzz[0]  = make_float2(cc, -sc);
        Rzz[5]  = make_float2(cc,  sc);
        Rzz[10] = make_float2(cc,  sc);
        Rzz[15] = make_float2(cc, -sc);
        float2 T[16], Bq[16];
        mat4mul(Ryy, Rxx, T);
        mat4mul(Rzz, T, Bq);

        float2 I2m[4] = { {1.f,0.f},{0.f,0.f},{0.f,0.f},{1.f,0.f} };
        float2 R[16], G[16];
        if (t == 0) kron22(U1[0], U1[1], R);
        else        kron22(I2m, U1[t + 1], R);
        mat4mul(Bq, R, G);
        if (t >= 10) {
            float2 L[16], G2[16];
            if (t == 18) kron22(U2[18], U2[19], L);
            else         kron22(U2[t], I2m, L);
            mat4mul(L, G, G2);
            for (int i = 0; i < 16; i++) G[i] = G2[i];
        }
        for (int i = 0; i < 16; i++) g_fused[t][i] = G[i];
    }
}

// ---------------- register-resident gate helpers ----------------
__device__ __forceinline__ void gate4(float2* v, const float2* m) {
    float2 a = v[0], b = v[1], c = v[2], d = v[3];
#pragma unroll
    for (int j = 0; j < 4; j++) {
        float2 r = cmul(m[4 * j], a);
        r = cadd(r, cmul(m[4 * j + 1], b));
        r = cadd(r, cmul(m[4 * j + 2], c));
        r = cadd(r, cmul(m[4 * j + 3], d));
        v[j] = r;
    }
}

// Apply two consecutive bonds: m1 on bits (LP+2, LP+1), then m2 on (LP+1, LP).
// Octet o covers amps base + j<<LP, j=0..7 (j2=bit LP+2 .. j0=bit LP).
template <int LP>
__device__ __forceinline__ void round2(float2* s, const float2* G1, const float2* G2,
                                       int tid, int nOct) {
    float2 m1[16], m2[16];
#pragma unroll
    for (int i = 0; i < 16; i++) { m1[i] = G1[i]; m2[i] = G2[i]; }
    for (int o = tid; o < nOct; o += 256) {
        int base = ((o >> LP) << (LP + 3)) | (o & ((1 << LP) - 1));
        float2 v[8];
#pragma unroll
        for (int j = 0; j < 8; j++) v[j] = s[SMAP(base + (j << LP))];
        float2 t[4];
        t[0] = v[0]; t[1] = v[2]; t[2] = v[4]; t[3] = v[6];
        gate4(t, m1);
        v[0] = t[0]; v[2] = t[1]; v[4] = t[2]; v[6] = t[3];
        t[0] = v[1]; t[1] = v[3]; t[2] = v[5]; t[3] = v[7];
        gate4(t, m1);
        v[1] = t[0]; v[3] = t[1]; v[5] = t[2]; v[7] = t[3];
        gate4(v, m2);
        gate4(v + 4, m2);
#pragma unroll
        for (int j = 0; j < 8; j++) s[SMAP(base + (j << LP))] = v[j];
    }
}

// Single bond at bit pair (PL+1, PL) over quads (for the odd bond out).
template <int PL>
__device__ __forceinline__ void round1(float2* s, const float2* G, int tid, int nQuad) {
    float2 m[16];
#pragma unroll
    for (int i = 0; i < 16; i++) m[i] = G[i];
    for (int p = tid; p < nQuad; p += 256) {
        int base = ((p >> PL) << (PL + 2)) | (p & ((1 << PL) - 1));
        float2 v[4];
#pragma unroll
        for (int j = 0; j < 4; j++) v[j] = s[SMAP(base + (j << PL))];
        gate4(v, m);
#pragma unroll
        for (int j = 0; j < 4; j++) s[SMAP(base + (j << PL))] = v[j];
    }
}

// ---------------- Pass H: bonds 0..8 on combined bits 11..2 ----------------
__global__ void pass_high(const float* __restrict__ x) {
    __shared__ float2 s[4096 + 512];
    const int b    = blockIdx.y;
    const int low0 = blockIdx.x * LOWC;
    const int tid  = threadIdx.x;
    const float* xb = x + (size_t)b * DIM;

    for (int e = tid; e < 4096; e += 256) {
        int l = e & (LOWC - 1), h = e >> 2;
        s[SMAP(e)] = make_float2(xb[h * 1024 + low0 + l], 0.f);
    }
    __syncthreads();
    round2<9>(s, g_fused[0], g_fused[1], tid, 512); __syncthreads();
    round2<7>(s, g_fused[2], g_fused[3], tid, 512); __syncthreads();
    round2<5>(s, g_fused[4], g_fused[5], tid, 512); __syncthreads();
    round2<3>(s, g_fused[6], g_fused[7], tid, 512); __syncthreads();
    round1<2>(s, g_fused[8], tid, 1024);            __syncthreads();

    float2* pb = g_psi + (size_t)b * DIM;
    for (int e = tid; e < 4096; e += 256) {
        int l = e & (LOWC - 1), h = e >> 2;
        pb[h * 1024 + low0 + l] = s[SMAP(e)];
    }
}

// ---------------- fp16 pack helpers ----------------
__device__ __forceinline__ uint32_t pk2(float a, float b) {
    __half ha = __float2half_rn(a), hb = __float2half_rn(b);
    return (uint32_t)__half_as_ushort(ha) | ((uint32_t)__half_as_ushort(hb) << 16);
}

// ---------------- Pass L: bonds 9..18 on bits 10..0; emit 7 packed planes ----------------
__global__ void pass_low() {
    __shared__ float2 s[2048 + 256];
    const int b = blockIdx.y;
    const size_t base = (size_t)b * DIM + (size_t)blockIdx.x * 2048;
    const int tid = threadIdx.x;

    for (int e = tid; e < 2048; e += 256) s[SMAP(e)] = g_psi[base + e];
    __syncthreads();
    round2<8>(s, g_fused[9],  g_fused[10], tid, 256); __syncthreads();
    round2<6>(s, g_fused[11], g_fused[12], tid, 256); __syncthreads();
    round2<4>(s, g_fused[13], g_fused[14], tid, 256); __syncthreads();
    round2<2>(s, g_fused[15], g_fused[16], tid, 256); __syncthreads();
    round2<0>(s, g_fused[17], g_fused[18], tid, 256); __syncthreads();

    // tile = k-pair (2*blockIdx.x, 2*blockIdx.x+1) x all 1024 cols
    const size_t ci0 = ((size_t)b << 19) + ((size_t)blockIdx.x << 10);
    for (int c = tid; c < 1024; c += 256) {
        float2 v0 = s[SMAP(c)];            // k even
        float2 v1 = s[SMAP(c + 1024)];     // k odd
        float r0 = v0.x, i0 = v0.y, r1 = v1.x, i1 = v1.y;
        float d0 = i0 - r0, d1 = i1 - r1;
        float s0 = r0 + i0, s1 = r1 + i1;
        __half rh0 = __float2half_rn(r0), rh1 = __float2half_rn(r1);
        __half ih0 = __float2half_rn(i0), ih1 = __float2half_rn(i1);
        __half dh0 = __float2half_rn(d0), dh1 = __float2half_rn(d1);
        size_t ci = ci0 + c;
        g_tp32[0 * PSTR + ci] = (uint32_t)__half_as_ushort(rh0) | ((uint32_t)__half_as_ushort(rh1) << 16);
        g_tp32[1 * PSTR + ci] = pk2(r0 - __half2float(rh0), r1 - __half2float(rh1));
        g_tp32[2 * PSTR + ci] = (uint32_t)__half_as_ushort(ih0) | ((uint32_t)__half_as_ushort(ih1) << 16);
        g_tp32[3 * PSTR + ci] = pk2(i0 - __half2float(ih0), i1 - __half2float(ih1));
        g_tp32[4 * PSTR + ci] = (uint32_t)__half_as_ushort(dh0) | ((uint32_t)__half_as_ushort(dh1) << 16);
        g_tp32[5 * PSTR + ci] = pk2(d0 - __half2float(dh0), d1 - __half2float(dh1));
        g_tp32[6 * PSTR + ci] = pk2(s0, s1);
    }
}

// ---------------- rdm GEMM v6: packed [kpair][col] planes, fp16 Gauss ----------------
// Block tile 64(a) x 128(c); warp 32x32; t1=Ar*Br, t2=Ai*Bi, t3=(Ai-Ar)*(Br+Bi).
#define AS 72            // A smem col-count stride (uint32), ≡8 mod 32 -> conflict-free
#define BS 136           // B stride
#define A_PL_B (8 * AS * 4)            // 2304 B per A plane (8 kpairs)
#define B_PL_B (8 * BS * 4)            // 4352 B per B plane
#define A_ALL_B (6 * A_PL_B)           // 13824
#define STG_B  (A_ALL_B + 3 * B_PL_B)  // 26880
#define NSTG   3
#define GEMM_SMEM (NSTG * STG_B)       // 80640

__device__ __forceinline__ void mma_f16(float* d, uint32_t a0, uint32_t a1,
                                        uint32_t a2, uint32_t a3,
                                        uint32_t b0, uint32_t b1) {
    asm volatile(
        "mma.sync.aligned.m16n8k16.row.col.f32.f16.f16.f32 "
        "{%0,%1,%2,%3},{%4,%5,%6,%7},{%8,%9},{%0,%1,%2,%3};"
        : "+f"(d[0]), "+f"(d[1]), "+f"(d[2]), "+f"(d[3])
        : "r"(a0), "r"(a1), "r"(a2), "r"(a3), "r"(b0), "r"(b1));
}
__device__ __forceinline__ void cp_async16(void* smem_ptr, const void* gptr) {
    uint32_t sa = (uint32_t)__cvta_generic_to_shared(smem_ptr);
    asm volatile("cp.async.cg.shared.global [%0], [%1], 16;" :: "r"(sa), "l"(gptr));
}
__device__ __forceinline__ void cp_commit() { asm volatile("cp.async.commit_group;"); }
__device__ __forceinline__ void cp_wait2()  { asm volatile("cp.async.wait_group 2;"); }

__global__ void __launch_bounds__(256, 2) rdm_gemm(float* __restrict__ out) {
    extern __shared__ char smem[];

    // decode linear block -> (col tile tcc of 128, row tile ta of 64), ta <= 2*tcc+1
    int tcc = 0, rem = blockIdx.x;
    while (rem >= 2 * tcc + 2) { rem -= 2 * tcc + 2; tcc++; }
    int ta = rem;

    const int b = blockIdx.y;
    const int a0b = ta * 64, c0b = tcc * 128;
    const int tid  = threadIdx.x;
    const int wid  = tid >> 5;
    const int lane = tid & 31;
    const int g    = lane >> 2;
    const int t4   = lane & 3;
    const int warpM = wid & 1;     // a offset 0/32
    const int warpN = wid >> 1;    // c offset 0/32/64/96

    float acc[3][2][4][4] = {};    // [product][mi][ni][reg]

    auto stage = [&](int kt) {
        char* sb = smem + (kt % NSTG) * STG_B;
        const int kr0 = kt * 8;
#pragma unroll
        for (int j = 0; j < 6; j++) {
            int cid = tid + j * 256;
            if (cid < 768) {                        // A: 6 planes x 8 kpairs x 16 chunks
                int pl = cid >> 7;
                int rm = cid & 127;
                int kp = rm >> 4, ch = rm & 15;
                const uint32_t* src = g_tp32 + (size_t)pl * PSTR + ((size_t)b << 19)
                                    + ((size_t)(kr0 + kp) << 10) + a0b + ch * 4;
                cp_async16(sb + pl * A_PL_B + kp * (AS * 4) + ch * 16, src);
            } else {                                // B: planes {rH=0,iH=2,sH=6} x 8 x 32
                int d2 = cid - 768;
                int p = d2 >> 8;
                int rm = d2 & 255;
                int kp = rm >> 5, ch = rm & 31;
                int gp = (p == 0) ? 0 : ((p == 1) ? 2 : 6);
                const uint32_t* src = g_tp32 + (size_t)gp * PSTR + ((size_t)b << 19)
                                    + ((size_t)(kr0 + kp) << 10) + c0b + ch * 4;
                cp_async16(sb + A_ALL_B + p * B_PL_B + kp * (BS * 4) + ch * 16, src);
            }
        }
        cp_commit();
    };

    stage(0);
    stage(1);
    stage(2);

    for (int kt = 0; kt < 64; kt++) {
        cp_wait2();
        __syncthreads();
        const char* sb = smem + (kt % NSTG) * STG_B;

#pragma unroll
        for (int p = 0; p < 3; p++) {
            const uint32_t* paH = (const uint32_t*)(sb + (2 * p) * A_PL_B);
            const uint32_t* paL = (const uint32_t*)(sb + (2 * p + 1) * A_PL_B);
            const uint32_t* pB  = (const uint32_t*)(sb + A_ALL_B + p * B_PL_B);

            uint32_t Ah[2][4], Al[2][4];
#pragma unroll
            for (int mi = 0; mi < 2; mi++) {
                int col = warpM * 32 + mi * 16 + g;
                Ah[mi][0] = paH[t4 * AS + col];
                Ah[mi][1] = paH[t4 * AS + col + 8];
                Ah[mi][2] = paH[(t4 + 4) * AS + col];
                Ah[mi][3] = paH[(t4 + 4) * AS + col + 8];
                Al[mi][0] = paL[t4 * AS + col];
                Al[mi][1] = paL[t4 * AS + col + 8];
                Al[mi][2] = paL[(t4 + 4) * AS + col];
                Al[mi][3] = paL[(t4 + 4) * AS + col + 8];
            }
            uint32_t Bf[4][2];
#pragma unroll
            for (int ni = 0; ni < 4; ni++) {
                int col = warpN * 32 + ni * 8 + g;
                Bf[ni][0] = pB[t4 * BS + col];
                Bf[ni][1] = pB[(t4 + 4) * BS + col];
            }
#pragma unroll
            for (int ni = 0; ni < 4; ni++)
#pragma unroll
                for (int mi = 0; mi < 2; mi++)
                    mma_f16(acc[p][mi][ni], Ah[mi][0], Ah[mi][1], Ah[mi][2], Ah[mi][3],
                            Bf[ni][0], Bf[ni][1]);
#pragma unroll
            for (int ni = 0; ni < 4; ni++)
#pragma unroll
                for (int mi = 0; mi < 2; mi++)
                    mma_f16(acc[p][mi][ni], Al[mi][0], Al[mi][1], Al[mi][2], Al[mi][3],
                            Bf[ni][0], Bf[ni][1]);
        }
        __syncthreads();

        if (kt + 3 < 64) stage(kt + 3);
        else             cp_commit();
    }

    // ---- epilogue: R = t1+t2, I = t3+t1-t2; exactly-once Hermitian writes ----
    float2* out2 = (float2*)out;
#pragma unroll
    for (int mi = 0; mi < 2; mi++)
#pragma unroll
        for (int ni = 0; ni < 4; ni++)
#pragma unroll
            for (int r = 0; r < 4; r++) {
                int a = a0b + warpM * 32 + mi * 16 + g + ((r & 2) ? 8 : 0);
                int c = c0b + warpN * 32 + ni * 8 + 2 * t4 + (r & 1);
                float t1 = acc[0][mi][ni][r];
                float t2 = acc[1][mi][ni][r];
                float t3 = acc[2][mi][ni][r];
                float vr = t1 + t2;
                float vi = t3 + t1 - t2;
                if (a <= c)
                    out2[(size_t)(b * 1024 + a) * 1024 + c] = make_float2(vr, vi);
                if (a < c)
                    out2[(size_t)(b * 1024 + c) * 1024 + a] = make_float2(vr, -vi);
            }
}

// ---------------- launch ----------------
extern "C" void kernel_launch(void* const* d_in, const int* in_sizes, int n_in,
                              void* d_out, int out_size) {
    const float* x = (const float*)d_in[0];
    const float* w = (const float*)d_in[1];
    float* out = (float*)d_out;

    cudaFuncSetAttribute(rdm_gemm, cudaFuncAttributeMaxDynamicSharedMemorySize, GEMM_SMEM);

    precompute_gates<<<1, 32>>>(w);
    pass_high<<<dim3(1024 / LOWC, BATCH), 256>>>(x);
    pass_low<<<dim3(512, BATCH), 256>>>();
    rdm_gemm<<<dim3(72, BATCH), 256, GEMM_SMEM>>>(out);
}

// round 9
// speedup vs baseline: 1.3789x; 1.2112x over previous
#include <cuda_runtime.h>
#include <cuda_fp16.h>
#include <math.h>
#include <stdint.h>

#define NQ    20
#define DIM   (1u << NQ)
#define BATCH 4
#define LOWC  4

// ---------------- global scratch ----------------
static __device__ float2 g_psi[(size_t)BATCH * DIM];   // state after pass_high
// 7 packed-fp16 planes [plane][b][kpair][col], uint32 = {k even (lo), k odd (hi)}
// planes: 0=rH 1=rL 2=iH 3=iL 4=dH 5=dL 6=sH   (d = i - r, s = r + i)
static __device__ uint32_t g_tp32[(size_t)7 * BATCH * (DIM / 2)];
static __device__ float2 g_fused[NQ - 1][16];          // fused 4x4 gates
#define PSTR ((size_t)BATCH << 19)                     // uint32s per plane

// ---------------- complex helpers ----------------
__device__ __forceinline__ float2 cmul(float2 a, float2 b) {
    return make_float2(a.x * b.x - a.y * b.y, a.x * b.y + a.y * b.x);
}
__device__ __forceinline__ float2 cadd(float2 a, float2 b) {
    return make_float2(a.x + b.x, a.y + b.y);
}
__device__ void mat2mul(const float2* A, const float2* B, float2* C) {
    for (int i = 0; i < 2; i++)
        for (int j = 0; j < 2; j++) {
            float2 s = make_float2(0.f, 0.f);
            for (int k = 0; k < 2; k++) s = cadd(s, cmul(A[i * 2 + k], B[k * 2 + j]));
            C[i * 2 + j] = s;
        }
}
__device__ void mat4mul(const float2* A, const float2* B, float2* C) {
    for (int i = 0; i < 4; i++)
        for (int j = 0; j < 4; j++) {
            float2 s = make_float2(0.f, 0.f);
            for (int k = 0; k < 4; k++) s = cadd(s, cmul(A[i * 4 + k], B[k * 4 + j]));
            C[i * 4 + j] = s;
        }
}
__device__ void kron22(const float2* A, const float2* B, float2* C) {
    for (int i2 = 0; i2 < 2; i2++)
        for (int i1 = 0; i1 < 2; i1++)
            for (int j2 = 0; j2 < 2; j2++)
                for (int j1 = 0; j1 < 2; j1++)
                    C[(i2 * 2 + i1) * 4 + (j2 * 2 + j1)] = cmul(A[i2 * 2 + j2], B[i1 * 2 + j1]);
}

// ---------------- gate precompute ----------------
__global__ void precompute_gates(const float* __restrict__ w) {
    const float WM = 0.6324555320336759f;  // sqrt(2/5)
    __shared__ float2 U1[NQ][4];
    __shared__ float2 U2[NQ][4];
    int t = threadIdx.x;
    if (t < NQ) {
        for (int layer = 0; layer < 2; layer++) {
            int base = (layer == 0) ? 0 : (6 * NQ - 3);
            float tx = w[base + 3 * t]     * WM;
            float ty = w[base + 3 * t + 1] * WM;
            float tz = w[base + 3 * t + 2] * WM;
            float cx = cosf(0.5f * tx), sx = sinf(0.5f * tx);
            float cy = cosf(0.5f * ty), sy = sinf(0.5f * ty);
            float cz = cosf(0.5f * tz), sz = sinf(0.5f * tz);
            float2 Rx[4] = { {cx,0.f}, {0.f,-sx}, {0.f,-sx}, {cx,0.f} };
            float2 Ry[4] = { {cy,0.f}, {-sy,0.f}, {sy,0.f},  {cy,0.f} };
            float2 Rz[4] = { {cz,-sz}, {0.f,0.f}, {0.f,0.f}, {cz,sz} };
            float2 T[4], U[4];
            mat2mul(Ry, Rx, T);
            mat2mul(Rz, T, U);
            float2* dst = (layer == 0) ? U1[t] : U2[t];
            for (int i = 0; i < 4; i++) dst[i] = U[i];
        }
    }
    __syncthreads();
    if (t < NQ - 1) {
        float a = w[3 * NQ + 3 * t]     * WM;
        float b = w[3 * NQ + 3 * t + 1] * WM;
        float c = w[3 * NQ + 3 * t + 2] * WM;
        float ca = cosf(0.5f * a), sa = sinf(0.5f * a);
        float cb = cosf(0.5f * b), sb = sinf(0.5f * b);
        float cc = cosf(0.5f * c), sc = sinf(0.5f * c);
        float2 Rxx[16], Ryy[16], Rzz[16];
        for (int i = 0; i < 16; i++) {
            Rxx[i] = make_float2(0.f, 0.f);
            Ryy[i] = make_float2(0.f, 0.f);
            Rzz[i] = make_float2(0.f, 0.f);
        }
        for (int i = 0; i < 4; i++) {
            Rxx[i * 4 + i] = make_float2(ca, 0.f);
            Ryy[i * 4 + i] = make_float2(cb, 0.f);
        }
        Rxx[3]  = make_float2(0.f, -sa);
        Rxx[6]  = make_float2(0.f, -sa);
        Rxx[9]  = make_float2(0.f, -sa);
        Rxx[12] = make_float2(0.f, -sa);
        Ryy[3]  = make_float2(0.f,  sb);
        Ryy[6]  = make_float2(0.f, -sb);
        Ryy[9]  = make_float2(0.f, -sb);
        Ryy[12] = make_float2(0.f,  sb);
        Rzz[0]  = make_float2(cc, -sc);
        Rzz[5]  = make_float2(cc,  sc);
        Rzz[10] = make_float2(cc,  sc);
        Rzz[15] = make_float2(cc, -sc);
        float2 T[16], Bq[16];
        mat4mul(Ryy, Rxx, T);
        mat4mul(Rzz, T, Bq);

        float2 I2m[4] = { {1.f,0.f},{0.f,0.f},{0.f,0.f},{1.f,0.f} };
        float2 R[16], G[16];
        if (t == 0) kron22(U1[0], U1[1], R);
        else        kron22(I2m, U1[t + 1], R);
        mat4mul(Bq, R, G);
        if (t >= 10) {
            float2 L[16], G2[16];
            if (t == 18) kron22(U2[18], U2[19], L);
            else         kron22(U2[t], I2m, L);
            mat4mul(L, G, G2);
            for (int i = 0; i < 16; i++) G[i] = G2[i];
        }
        for (int i = 0; i < 16; i++) g_fused[t][i] = G[i];
    }
}

// ---------------- 2q gate on shared tile (lean, proven) ----------------
__device__ __forceinline__ void apply2q(float2* s, int nquads, int pl,
                                        const float2* __restrict__ Mg,
                                        int tid, int nth) {
    float2 m[16];
#pragma unroll
    for (int i = 0; i < 16; i++) m[i] = Mg[i];
    for (int p = tid; p < nquads; p += nth) {
        int lowm = p & ((1 << pl) - 1);
        int i0 = ((p >> pl) << (pl + 2)) | lowm;
        float2 v0 = s[i0];
        float2 v1 = s[i0 | (1 << pl)];
        float2 v2 = s[i0 | (2 << pl)];
        float2 v3 = s[i0 | (3 << pl)];
#pragma unroll
        for (int j = 0; j < 4; j++) {
            float2 m0 = m[j * 4], m1 = m[j * 4 + 1], m2 = m[j * 4 + 2], m3 = m[j * 4 + 3];
            float rr = m0.x * v0.x - m0.y * v0.y + m1.x * v1.x - m1.y * v1.y
                     + m2.x * v2.x - m2.y * v2.y + m3.x * v3.x - m3.y * v3.y;
            float ri = m0.x * v0.y + m0.y * v0.x + m1.x * v1.y + m1.y * v1.x
                     + m2.x * v2.y + m2.y * v2.x + m3.x * v3.y + m3.y * v3.x;
            s[i0 | (j << pl)] = make_float2(rr, ri);
        }
    }
}

// ---------------- Pass H: bonds 0..8 on combined bits 11..2 ----------------
__global__ void pass_high(const float* __restrict__ x) {
    __shared__ float2 s[1024 * LOWC];
    const int b    = blockIdx.y;
    const int low0 = blockIdx.x * LOWC;
    const int tid  = threadIdx.x;
    const float* xb = x + (size_t)b * DIM;

    for (int e = tid; e < 1024 * LOWC; e += blockDim.x) {
        int l = e & (LOWC - 1), h = e >> 2;
        s[e] = make_float2(xb[h * 1024 + low0 + l], 0.f);
    }
    __syncthreads();
    for (int q = 0; q < 9; q++) {
        apply2q(s, 1024, (8 - q) + 2, g_fused[q], tid, blockDim.x);
        __syncthreads();
    }
    float2* pb = g_psi + (size_t)b * DIM;
    for (int e = tid; e < 1024 * LOWC; e += blockDim.x) {
        int l = e & (LOWC - 1), h = e >> 2;
        pb[h * 1024 + low0 + l] = s[e];
    }
}

// ---------------- fp16 pack helper ----------------
__device__ __forceinline__ uint32_t pk2(float a, float b) {
    __half ha = __float2half_rn(a), hb = __float2half_rn(b);
    return (uint32_t)__half_as_ushort(ha) | ((uint32_t)__half_as_ushort(hb) << 16);
}

// ---------------- Pass L: bonds 9..18 on bits 10..0; emit 7 packed planes ----------------
__global__ void pass_low() {
    __shared__ float2 s[2048];
    const int b = blockIdx.y;
    const size_t base = (size_t)b * DIM + (size_t)blockIdx.x * 2048;
    const int tid = threadIdx.x;

    for (int e = tid; e < 2048; e += blockDim.x) s[e] = g_psi[base + e];
    __syncthreads();
    for (int q = 9; q < 19; q++) {
        apply2q(s, 512, 18 - q, g_fused[q], tid, blockDim.x);
        __syncthreads();
    }

    // tile = k-pair (2*blockIdx.x, 2*blockIdx.x+1) x all 1024 cols
    const size_t ci0 = ((size_t)b << 19) + ((size_t)blockIdx.x << 10);
    for (int c = tid; c < 1024; c += blockDim.x) {
        float2 v0 = s[c];            // k even
        float2 v1 = s[c + 1024];     // k odd
        float r0 = v0.x, i0 = v0.y, r1 = v1.x, i1 = v1.y;
        float d0 = i0 - r0, d1 = i1 - r1;
        float s0 = r0 + i0, s1 = r1 + i1;
        __half rh0 = __float2half_rn(r0), rh1 = __float2half_rn(r1);
        __half ih0 = __float2half_rn(i0), ih1 = __float2half_rn(i1);
        __half dh0 = __float2half_rn(d0), dh1 = __float2half_rn(d1);
        size_t ci = ci0 + c;
        g_tp32[0 * PSTR + ci] = (uint32_t)__half_as_ushort(rh0) | ((uint32_t)__half_as_ushort(rh1) << 16);
        g_tp32[1 * PSTR + ci] = pk2(r0 - __half2float(rh0), r1 - __half2float(rh1));
        g_tp32[2 * PSTR + ci] = (uint32_t)__half_as_ushort(ih0) | ((uint32_t)__half_as_ushort(ih1) << 16);
        g_tp32[3 * PSTR + ci] = pk2(i0 - __half2float(ih0), i1 - __half2float(ih1));
        g_tp32[4 * PSTR + ci] = (uint32_t)__half_as_ushort(dh0) | ((uint32_t)__half_as_ushort(dh1) << 16);
        g_tp32[5 * PSTR + ci] = pk2(d0 - __half2float(dh0), d1 - __half2float(dh1));
        g_tp32[6 * PSTR + ci] = pk2(s0, s1);
    }
}

// ---------------- rdm GEMM v7: k32 stages, double buffer, fp16 Gauss ----------------
// Block tile 64(a) x 128(c); warp 32x32; t1=Ar*Br, t2=Ai*Bi, t3=(Ai-Ar)*(Br+Bi).
#define AS 72            // A smem col stride (uint32), ≡8 mod 32 -> conflict-free
#define BS 136           // B stride
#define A_PL_B (16 * AS * 4)           // 4608 B per A plane (16 kpairs = k32)
#define B_PL_B (16 * BS * 4)           // 8704 B per B plane
#define A_ALL_B (6 * A_PL_B)           // 27648
#define STG_B  (A_ALL_B + 3 * B_PL_B)  // 53760
#define NSTG   2
#define GEMM_SMEM (NSTG * STG_B)       // 107520

__device__ __forceinline__ void mma_f16(float* d, uint32_t a0, uint32_t a1,
                                        uint32_t a2, uint32_t a3,
                                        uint32_t b0, uint32_t b1) {
    asm volatile(
        "mma.sync.aligned.m16n8k16.row.col.f32.f16.f16.f32 "
        "{%0,%1,%2,%3},{%4,%5,%6,%7},{%8,%9},{%0,%1,%2,%3};"
        : "+f"(d[0]), "+f"(d[1]), "+f"(d[2]), "+f"(d[3])
        : "r"(a0), "r"(a1), "r"(a2), "r"(a3), "r"(b0), "r"(b1));
}
__device__ __forceinline__ void cp_async16(void* smem_ptr, const void* gptr) {
    uint32_t sa = (uint32_t)__cvta_generic_to_shared(smem_ptr);
    asm volatile("cp.async.cg.shared.global [%0], [%1], 16;" :: "r"(sa), "l"(gptr));
}
__device__ __forceinline__ void cp_commit() { asm volatile("cp.async.commit_group;"); }
__device__ __forceinline__ void cp_wait1()  { asm volatile("cp.async.wait_group 1;"); }

__global__ void __launch_bounds__(256, 2) rdm_gemm(float* __restrict__ out) {
    extern __shared__ char smem[];

    // decode linear block -> (col tile tcc of 128, row tile ta of 64), ta <= 2*tcc+1
    int tcc = 0, rem = blockIdx.x;
    while (rem >= 2 * tcc + 2) { rem -= 2 * tcc + 2; tcc++; }
    int ta = rem;

    const int b = blockIdx.y;
    const int a0b = ta * 64, c0b = tcc * 128;
    const int tid  = threadIdx.x;
    const int wid  = tid >> 5;
    const int lane = tid & 31;
    const int g    = lane >> 2;
    const int t4   = lane & 3;
    const int warpM = wid & 1;     // a offset 0/32
    const int warpN = wid >> 1;    // c offset 0/32/64/96

    float acc[3][2][4][4] = {};    // [product][mi][ni][reg]

    // one stage = k32 = 16 kpairs: A 6 planes x 16 kp x 16 chunks; B 3 x 16 x 32
    auto stage = [&](int st) {
        char* sb = smem + (st & 1) * STG_B;
        const int kr0 = st * 16;
#pragma unroll
        for (int j = 0; j < 12; j++) {
            int cid = tid + j * 256;
            if (cid < 1536) {                       // A
                int pl = cid >> 8;
                int rm = cid & 255;
                int kp = rm >> 4, ch = rm & 15;
                const uint32_t* src = g_tp32 + (size_t)pl * PSTR + ((size_t)b << 19)
                                    + ((size_t)(kr0 + kp) << 10) + a0b + ch * 4;
                cp_async16(sb + pl * A_PL_B + kp * (AS * 4) + ch * 16, src);
            } else {                                // B: planes {rH=0,iH=2,sH=6}
                int d2 = cid - 1536;
                int p = d2 >> 9;
                int rm = d2 & 511;
                int kp = rm >> 5, ch = rm & 31;
                int gp = (p == 0) ? 0 : ((p == 1) ? 2 : 6);
                const uint32_t* src = g_tp32 + (size_t)gp * PSTR + ((size_t)b << 19)
                                    + ((size_t)(kr0 + kp) << 10) + c0b + ch * 4;
                cp_async16(sb + A_ALL_B + p * B_PL_B + kp * (BS * 4) + ch * 16, src);
            }
        }
        cp_commit();
    };

    stage(0);
    stage(1);

    for (int st = 0; st < 32; st++) {
        cp_wait1();
        __syncthreads();
        const char* sb = smem + (st & 1) * STG_B;

#pragma unroll
        for (int half = 0; half < 2; half++) {      // two k16 sub-chunks
            const int kofs = half * 8;              // kpair offset
#pragma unroll
            for (int p = 0; p < 3; p++) {
                const uint32_t* paH = (const uint32_t*)(sb + (2 * p) * A_PL_B) + kofs * AS;
                const uint32_t* paL = (const uint32_t*)(sb + (2 * p + 1) * A_PL_B) + kofs * AS;
                const uint32_t* pB  = (const uint32_t*)(sb + A_ALL_B + p * B_PL_B) + kofs * BS;

                uint32_t Ah[2][4], Al[2][4];
#pragma unroll
                for (int mi = 0; mi < 2; mi++) {
                    int col = warpM * 32 + mi * 16 + g;
                    Ah[mi][0] = paH[t4 * AS + col];
                    Ah[mi][1] = paH[t4 * AS + col + 8];
                    Ah[mi][2] = paH[(t4 + 4) * AS + col];
                    Ah[mi][3] = paH[(t4 + 4) * AS + col + 8];
                    Al[mi][0] = paL[t4 * AS + col];
                    Al[mi][1] = paL[t4 * AS + col + 8];
                    Al[mi][2] = paL[(t4 + 4) * AS + col];
                    Al[mi][3] = paL[(t4 + 4) * AS + col + 8];
                }
                uint32_t Bf[4][2];
#pragma unroll
                for (int ni = 0; ni < 4; ni++) {
                    int col = warpN * 32 + ni * 8 + g;
                    Bf[ni][0] = pB[t4 * BS + col];
                    Bf[ni][1] = pB[(t4 + 4) * BS + col];
                }
#pragma unroll
                for (int ni = 0; ni < 4; ni++)
#pragma unroll
                    for (int mi = 0; mi < 2; mi++)
                        mma_f16(acc[p][mi][ni], Ah[mi][0], Ah[mi][1], Ah[mi][2], Ah[mi][3],
                                Bf[ni][0], Bf[ni][1]);
#pragma unroll
                for (int ni = 0; ni < 4; ni++)
#pragma unroll
                    for (int mi = 0; mi < 2; mi++)
                        mma_f16(acc[p][mi][ni], Al[mi][0], Al[mi][1], Al[mi][2], Al[mi][3],
                                Bf[ni][0], Bf[ni][1]);
            }
        }
        __syncthreads();

        if (st + 2 < 32) stage(st + 2);
        else             cp_commit();
    }

    // ---- epilogue: R = t1+t2, I = t3+t1-t2; exactly-once Hermitian writes ----
    float2* out2 = (float2*)out;
#pragma unroll
    for (int mi = 0; mi < 2; mi++)
#pragma unroll
        for (int ni = 0; ni < 4; ni++)
#pragma unroll
            for (int r = 0; r < 4; r++) {
                int a = a0b + warpM * 32 + mi * 16 + g + ((r & 2) ? 8 : 0);
                int c = c0b + warpN * 32 + ni * 8 + 2 * t4 + (r & 1);
                float t1 = acc[0][mi][ni][r];
                float t2 = acc[1][mi][ni][r];
                float t3 = acc[2][mi][ni][r];
                float vr = t1 + t2;
                float vi = t3 + t1 - t2;
                if (a <= c)
                    out2[(size_t)(b * 1024 + a) * 1024 + c] = make_float2(vr, vi);
                if (a < c)
                    out2[(size_t)(b * 1024 + c) * 1024 + a] = make_float2(vr, -vi);
            }
}

// ---------------- launch ----------------
extern "C" void kernel_launch(void* const* d_in, const int* in_sizes, int n_in,
                              void* d_out, int out_size) {
    const float* x = (const float*)d_in[0];
    const float* w = (const float*)d_in[1];
    float* out = (float*)d_out;

    cudaFuncSetAttribute(rdm_gemm, cudaFuncAttributeMaxDynamicSharedMemorySize, GEMM_SMEM);

    precompute_gates<<<1, 32>>>(w);
    pass_high<<<dim3(1024 / LOWC, BATCH), 256>>>(x);
    pass_low<<<dim3(512, BATCH), 256>>>();
    rdm_gemm<<<dim3(72, BATCH), 256, GEMM_SMEM>>>(out);
}